// round 5
// baseline (speedup 1.0000x reference)
#include <cuda_runtime.h>
#include <cuda_bf16.h>
#include <cstdint>

// ---------------------------------------------------------------------------
// Problem constants
// ---------------------------------------------------------------------------
#define D_MODEL   512
#define D_HALF    256
#define D_FF      1024
#define D_FF2     2048
#define N_LAYERS  2
#define N_EXPERTS 8
#define N_TOKENS  2048           // B*S = 2*1024
#define CAP       2048           // per-expert capacity (worst case)

// ---------------------------------------------------------------------------
// Static scratch (no allocations allowed)
// ---------------------------------------------------------------------------
__device__ float d_Xg [(size_t)N_EXPERTS * CAP * D_MODEL];   // gathered inputs
__device__ float d_H  [(size_t)N_EXPERTS * CAP * D_FF];      // hidden state
__device__ float d_A2 [(size_t)N_EXPERTS * CAP * D_FF2];     // gelu(h@W1)
__device__ float d_H2 [(size_t)N_EXPERTS * CAP * D_FF];      // h2
__device__ float d_Ob [(size_t)N_EXPERTS * CAP * D_MODEL];   // expert out pre-LN
__device__ int   d_counts[N_EXPERTS];
__device__ int   d_tlist[N_EXPERTS * CAP];

// ---------------------------------------------------------------------------
// Helpers
// ---------------------------------------------------------------------------
__device__ __forceinline__ float gelu_f(float v) {
    return 0.5f * v * (1.0f + erff(v * 0.70710678118654752440f));
}

__device__ __forceinline__ void tf_round(uint32_t& a, uint32_t& b, int r) {
    a += b;
    b = (b << r) | (b >> (32 - r));
    b ^= a;
}

// JAX threefry2x32, key schedule exactly as jax/_src/prng.py
__device__ __forceinline__ uint2 threefry2x32(uint32_t k0, uint32_t k1,
                                              uint32_t x0, uint32_t x1) {
    uint32_t ks0 = k0, ks1 = k1, ks2 = k0 ^ k1 ^ 0x1BD11BDAu;
    x0 += ks0; x1 += ks1;
    tf_round(x0, x1, 13); tf_round(x0, x1, 15); tf_round(x0, x1, 26); tf_round(x0, x1, 6);
    x0 += ks1; x1 += ks2 + 1u;
    tf_round(x0, x1, 17); tf_round(x0, x1, 29); tf_round(x0, x1, 16); tf_round(x0, x1, 24);
    x0 += ks2; x1 += ks0 + 2u;
    tf_round(x0, x1, 13); tf_round(x0, x1, 15); tf_round(x0, x1, 26); tf_round(x0, x1, 6);
    x0 += ks0; x1 += ks1 + 3u;
    tf_round(x0, x1, 17); tf_round(x0, x1, 29); tf_round(x0, x1, 16); tf_round(x0, x1, 24);
    x0 += ks1; x1 += ks2 + 4u;
    tf_round(x0, x1, 13); tf_round(x0, x1, 15); tf_round(x0, x1, 26); tf_round(x0, x1, 6);
    x0 += ks2; x1 += ks0 + 5u;
    return make_uint2(x0, x1);
}

// Tree reduction over 256 threads; every thread returns the total.
__device__ __forceinline__ float reduce256(float v, float* red) {
    int t = threadIdx.x;
    red[t] = v;
    __syncthreads();
    #pragma unroll
    for (int s = 128; s > 0; s >>= 1) {
        if (t < s) red[t] += red[t + s];
        __syncthreads();
    }
    float r = red[0];
    __syncthreads();
    return r;
}

// ---------------------------------------------------------------------------
// Kernel: zero routing counters
// ---------------------------------------------------------------------------
__global__ void zero_counts_kernel() {
    if (threadIdx.x < N_EXPERTS) d_counts[threadIdx.x] = 0;
}

// ---------------------------------------------------------------------------
// Kernel: policy head + Gumbel top-2 routing.  One block per token.
// ---------------------------------------------------------------------------
__global__ __launch_bounds__(256)
void routing_kernel(const float* __restrict__ x,
                    const float* __restrict__ pw1, const float* __restrict__ pb1,
                    const float* __restrict__ pg1, const float* __restrict__ pbb1,
                    const float* __restrict__ pw2, const float* __restrict__ pb2) {
    __shared__ float xs[D_MODEL];
    __shared__ float red[256];
    __shared__ float gbuf[D_HALF];
    __shared__ float scores[N_EXPERTS];

    int token = blockIdx.x;
    int t = threadIdx.x;

    for (int i = t; i < D_MODEL; i += 256) xs[i] = x[(size_t)token * D_MODEL + i];
    __syncthreads();

    // h1[t] = x . pw1[:,t] + pb1[t]    (t in [0,256))
    float acc = pb1[t];
    #pragma unroll 4
    for (int k = 0; k < D_MODEL; k++)
        acc = fmaf(xs[k], pw1[k * D_HALF + t], acc);

    // LayerNorm over 256
    float mean = reduce256(acc, red) * (1.0f / D_HALF);
    float d = acc - mean;
    float var = reduce256(d * d, red) * (1.0f / D_HALF);
    float hn = d * rsqrtf(var + 1e-5f) * pg1[t] + pbb1[t];
    gbuf[t] = gelu_f(hn);
    __syncthreads();

    if (t < N_EXPERTS) {
        float lg = pb2[t];
        #pragma unroll 4
        for (int j = 0; j < D_HALF; j++)
            lg = fmaf(gbuf[j], pw2[j * N_EXPERTS + t], lg);

        // Gumbel noise: jax.random.uniform(key(42), (2,1024,8)) bit-exact,
        // partitionable threefry (modern JAX default):
        //   per-element counter (hi=0, lo=i); 32-bit output = out0 ^ out1
        //   (XOR-fold of the two threefry2x32 output words).
        uint32_t idx = (uint32_t)(token * N_EXPERTS + t);   // flat index < 16384
        uint2 r = threefry2x32(0u, 42u, 0u, idx);
        uint32_t bits = r.x ^ r.y;
        float u = __uint_as_float((bits >> 9) | 0x3f800000u) - 1.0f;
        float gn = -logf(-logf(u + 1e-10f) + 1e-10f);
        scores[t] = lg + gn;     // TEMP = 1.0
    }
    __syncthreads();

    if (t == 0) {
        int e1 = 0; float v1 = scores[0];
        #pragma unroll
        for (int e = 1; e < N_EXPERTS; e++)
            if (scores[e] > v1) { v1 = scores[e]; e1 = e; }
        int e2 = -1; float v2 = -1e30f;
        #pragma unroll
        for (int e = 0; e < N_EXPERTS; e++) {
            if (e == e1) continue;
            if (scores[e] > v2) { v2 = scores[e]; e2 = e; }
        }
        int p = atomicAdd(&d_counts[e1], 1);
        d_tlist[e1 * CAP + p] = token;
        p = atomicAdd(&d_counts[e2], 1);
        d_tlist[e2 * CAP + p] = token;
    }
}

// ---------------------------------------------------------------------------
// Kernel: gather selected token rows into per-expert dense buffers
// grid (CAP, N_EXPERTS), 128 threads
// ---------------------------------------------------------------------------
__global__ void gather_kernel(const float* __restrict__ x) {
    int m = blockIdx.x, e = blockIdx.y;
    if (m >= d_counts[e]) return;
    int token = d_tlist[e * CAP + m];
    const float4* src = (const float4*)(x + (size_t)token * D_MODEL);
    float4* dst = (float4*)(d_Xg + ((size_t)e * CAP + m) * D_MODEL);
    dst[threadIdx.x] = src[threadIdx.x];   // 128 * 16B = 512 floats
}

// ---------------------------------------------------------------------------
// Generic per-expert SGEMM: C[e] = act(A[e] @ B[e] + bias[e])
// A: [M_e, K] row-major, B: [K, N] row-major. 128x128x8 tile, 8x8 microtile.
// grid (N/128, CAP/128, N_EXPERTS), 256 threads. Rows >= count are skipped.
// ---------------------------------------------------------------------------
template<int ACT>   // 0 = none, 1 = exact GELU
__global__ __launch_bounds__(256)
void sgemm_kernel(const float* __restrict__ Aall, long strideA,
                  const float* __restrict__ Ball, long strideB,
                  const float* __restrict__ biasAll, long strideBias,
                  float* __restrict__ Call, long strideC,
                  int N, int K) {
    const int BM = 128, BN = 128, BK = 8, TM = 8, TN = 8;
    int e = blockIdx.z;
    int M = d_counts[e];
    int m0 = blockIdx.y * BM;
    if (m0 >= M) return;
    int n0 = blockIdx.x * BN;

    const float* A = Aall + (long)e * strideA;
    const float* B = Ball + (long)e * strideB;
    const float* bias = biasAll + (long)e * strideBias;
    float* C = Call + (long)e * strideC;

    __shared__ float As[BK][BM];
    __shared__ float Bs[BK][BN];

    int tid = threadIdx.x;
    int arow = tid >> 1;              // 0..127
    int acol = (tid & 1) * 4;         // 0 or 4
    int brow = tid >> 5;              // 0..7
    int bcol = (tid & 31) * 4;        // 0..124

    int tx = tid & 15;                // n-dir
    int ty = tid >> 4;                // m-dir

    float acc[TM][TN];
    #pragma unroll
    for (int i = 0; i < TM; i++)
        #pragma unroll
        for (int j = 0; j < TN; j++) acc[i][j] = 0.0f;

    for (int k0 = 0; k0 < K; k0 += BK) {
        float4 av = make_float4(0.f, 0.f, 0.f, 0.f);
        if (m0 + arow < M)
            av = *reinterpret_cast<const float4*>(&A[(long)(m0 + arow) * K + k0 + acol]);
        As[acol + 0][arow] = av.x;
        As[acol + 1][arow] = av.y;
        As[acol + 2][arow] = av.z;
        As[acol + 3][arow] = av.w;
        float4 bv = *reinterpret_cast<const float4*>(&B[(long)(k0 + brow) * N + n0 + bcol]);
        *reinterpret_cast<float4*>(&Bs[brow][bcol]) = bv;
        __syncthreads();

        #pragma unroll
        for (int kk = 0; kk < BK; kk++) {
            float4 ra0 = *reinterpret_cast<const float4*>(&As[kk][ty * TM]);
            float4 ra1 = *reinterpret_cast<const float4*>(&As[kk][ty * TM + 4]);
            float4 rb0 = *reinterpret_cast<const float4*>(&Bs[kk][tx * TN]);
            float4 rb1 = *reinterpret_cast<const float4*>(&Bs[kk][tx * TN + 4]);
            float ra[TM] = {ra0.x, ra0.y, ra0.z, ra0.w, ra1.x, ra1.y, ra1.z, ra1.w};
            float rb[TN] = {rb0.x, rb0.y, rb0.z, rb0.w, rb1.x, rb1.y, rb1.z, rb1.w};
            #pragma unroll
            for (int i = 0; i < TM; i++)
                #pragma unroll
                for (int j = 0; j < TN; j++)
                    acc[i][j] = fmaf(ra[i], rb[j], acc[i][j]);
        }
        __syncthreads();
    }

    #pragma unroll
    for (int i = 0; i < TM; i++) {
        int m = m0 + ty * TM + i;
        if (m >= M) continue;
        #pragma unroll
        for (int j = 0; j < TN; j++) {
            int n = n0 + tx * TN + j;
            float v = acc[i][j] + bias[n];
            if (ACT == 1) v = gelu_f(v);
            C[(long)m * N + n] = v;
        }
    }
}

// ---------------------------------------------------------------------------
// Kernel: per-row LN of h2, sigmoid gate from h, residual update.
// grid (CAP, N_EXPERTS), 256 threads. 1024 elems / row.
// ---------------------------------------------------------------------------
__global__ __launch_bounds__(256)
void lngate_kernel(const float* __restrict__ ng, const float* __restrict__ nb,
                   const float* __restrict__ gwv) {
    __shared__ float red[256];
    int m = blockIdx.x, e = blockIdx.y;
    if (m >= d_counts[e]) return;
    int t = threadIdx.x;

    float* h = d_H + ((size_t)e * CAP + m) * D_FF;
    const float* h2 = d_H2 + ((size_t)e * CAP + m) * D_FF;
    const float* ng_e = ng + (size_t)e * (N_LAYERS * D_FF);
    const float* nb_e = nb + (size_t)e * (N_LAYERS * D_FF);
    const float* gw_e = gwv + (size_t)e * (N_LAYERS * D_FF);

    float hv[4], h2v[4];
    float s = 0.f, sq = 0.f, dot = 0.f;
    #pragma unroll
    for (int c = 0; c < 4; c++) {
        int i = t + c * 256;
        hv[c] = h[i];
        h2v[c] = h2[i];
        s += h2v[c];
        dot = fmaf(hv[c], gw_e[i], dot);
    }
    float mean = reduce256(s, red) * (1.0f / D_FF);
    #pragma unroll
    for (int c = 0; c < 4; c++) { float d = h2v[c] - mean; sq += d * d; }
    float var = reduce256(sq, red) * (1.0f / D_FF);
    float dtot = reduce256(dot, red);
    float gate = 1.0f / (1.0f + expf(-dtot));
    float rstd = rsqrtf(var + 1e-5f);

    #pragma unroll
    for (int c = 0; c < 4; c++) {
        int i = t + c * 256;
        float hn = (h2v[c] - mean) * rstd * ng_e[i] + nb_e[i];
        h[i] = hv[c] + gate * hn;
    }
}

// ---------------------------------------------------------------------------
// Kernel: final residual LN + scatter-add into output.
// grid (CAP, N_EXPERTS), 256 threads. 512 elems / row.
// ---------------------------------------------------------------------------
__global__ __launch_bounds__(256)
void final_kernel(const float* __restrict__ x,
                  const float* __restrict__ fng, const float* __restrict__ fnb,
                  float* __restrict__ out) {
    __shared__ float red[256];
    int m = blockIdx.x, e = blockIdx.y;
    if (m >= d_counts[e]) return;
    int t = threadIdx.x;
    int token = d_tlist[e * CAP + m];

    const float* orow = d_Ob + ((size_t)e * CAP + m) * D_MODEL;
    const float* xrow = x + (size_t)token * D_MODEL;
    const float* g = fng + (size_t)e * D_MODEL;
    const float* b = fnb + (size_t)e * D_MODEL;

    float v[2];
    float s = 0.f, sq = 0.f;
    #pragma unroll
    for (int c = 0; c < 2; c++) {
        int i = t + c * 256;
        v[c] = xrow[i] + orow[i];
        s += v[c];
    }
    float mean = reduce256(s, red) * (1.0f / D_MODEL);
    #pragma unroll
    for (int c = 0; c < 2; c++) { float d = v[c] - mean; sq += d * d; }
    float var = reduce256(sq, red) * (1.0f / D_MODEL);
    float rstd = rsqrtf(var + 1e-5f);

    #pragma unroll
    for (int c = 0; c < 2; c++) {
        int i = t + c * 256;
        float y = (v[c] - mean) * rstd * g[i] + b[i];
        atomicAdd(&out[(size_t)token * D_MODEL + i], y);  // exactly 2 adds/elem
    }
}

// ---------------------------------------------------------------------------
// Launch
// ---------------------------------------------------------------------------
extern "C" void kernel_launch(void* const* d_in, const int* in_sizes, int n_in,
                              void* d_out, int out_size) {
    const float* x    = (const float*)d_in[0];
    const float* pw1  = (const float*)d_in[1];
    const float* pb1  = (const float*)d_in[2];
    const float* pg1  = (const float*)d_in[3];
    const float* pbb1 = (const float*)d_in[4];
    const float* pw2  = (const float*)d_in[5];
    const float* pb2  = (const float*)d_in[6];
    const float* Win  = (const float*)d_in[7];
    const float* b_in = (const float*)d_in[8];
    const float* W1   = (const float*)d_in[9];
    const float* b1   = (const float*)d_in[10];
    const float* W2   = (const float*)d_in[11];
    const float* b2   = (const float*)d_in[12];
    const float* ng   = (const float*)d_in[13];
    const float* nb   = (const float*)d_in[14];
    const float* gw   = (const float*)d_in[15];
    const float* Wout = (const float*)d_in[16];
    const float* bout = (const float*)d_in[17];
    const float* fng  = (const float*)d_in[18];
    const float* fnb  = (const float*)d_in[19];
    float* out = (float*)d_out;

    float *Xg, *H, *A2, *H2, *Ob;
    cudaGetSymbolAddress((void**)&Xg, d_Xg);
    cudaGetSymbolAddress((void**)&H,  d_H);
    cudaGetSymbolAddress((void**)&A2, d_A2);
    cudaGetSymbolAddress((void**)&H2, d_H2);
    cudaGetSymbolAddress((void**)&Ob, d_Ob);

    cudaMemsetAsync(out, 0, (size_t)out_size * sizeof(float), 0);
    zero_counts_kernel<<<1, 32>>>();
    routing_kernel<<<N_TOKENS, 256>>>(x, pw1, pb1, pg1, pbb1, pw2, pb2);
    gather_kernel<<<dim3(CAP, N_EXPERTS), 128>>>(x);

    // H = Xg @ Win + b_in                          [M,512]x[512,1024]
    sgemm_kernel<0><<<dim3(D_FF / 128, CAP / 128, N_EXPERTS), 256>>>(
        Xg, (long)CAP * D_MODEL,
        Win, (long)D_MODEL * D_FF,
        b_in, (long)D_FF,
        H, (long)CAP * D_FF,
        D_FF, D_MODEL);

    for (int l = 0; l < N_LAYERS; l++) {
        // A2 = gelu(H @ W1[l] + b1[l])             [M,1024]x[1024,2048]
        sgemm_kernel<1><<<dim3(D_FF2 / 128, CAP / 128, N_EXPERTS), 256>>>(
            H, (long)CAP * D_FF,
            W1 + (long)l * D_FF * D_FF2, (long)N_LAYERS * D_FF * D_FF2,
            b1 + (long)l * D_FF2, (long)N_LAYERS * D_FF2,
            A2, (long)CAP * D_FF2,
            D_FF2, D_FF);
        // H2 = A2 @ W2[l] + b2[l]                  [M,2048]x[2048,1024]
        sgemm_kernel<0><<<dim3(D_FF / 128, CAP / 128, N_EXPERTS), 256>>>(
            A2, (long)CAP * D_FF2,
            W2 + (long)l * D_FF2 * D_FF, (long)N_LAYERS * D_FF2 * D_FF,
            b2 + (long)l * D_FF, (long)N_LAYERS * D_FF,
            H2, (long)CAP * D_FF,
            D_FF, D_FF2);
        // H += sigmoid(H.gw) * LN(H2)
        lngate_kernel<<<dim3(CAP, N_EXPERTS), 256>>>(
            ng + (long)l * D_FF, nb + (long)l * D_FF, gw + (long)l * D_FF);
    }

    // Ob = H @ Wout + bout                         [M,1024]x[1024,512]
    sgemm_kernel<0><<<dim3(D_MODEL / 128, CAP / 128, N_EXPERTS), 256>>>(
        H, (long)CAP * D_FF,
        Wout, (long)D_FF * D_MODEL,
        bout, (long)D_MODEL,
        Ob, (long)CAP * D_MODEL,
        D_MODEL, D_FF);

    // out[token] += LN(x + Ob)
    final_kernel<<<dim3(CAP, N_EXPERTS), 256>>>(x, fng, fnb, out);
}

// round 8
// speedup vs baseline: 3.0206x; 3.0206x over previous
#include <cuda_runtime.h>
#include <cuda_bf16.h>
#include <cstdint>

// ---------------------------------------------------------------------------
// Problem constants
// ---------------------------------------------------------------------------
#define D_MODEL   512
#define D_HALF    256
#define D_FF      1024
#define D_FF2     2048
#define N_LAYERS  2
#define N_EXPERTS 8
#define N_TOKENS  2048
#define CAP       2048

// ---------------------------------------------------------------------------
// Static scratch (no allocations allowed)
// ---------------------------------------------------------------------------
__device__ float d_Xg [(size_t)N_EXPERTS * CAP * D_MODEL];
__device__ float d_H  [(size_t)N_EXPERTS * CAP * D_FF];
__device__ float d_A2 [(size_t)N_EXPERTS * CAP * D_FF2];
__device__ float d_H2 [(size_t)N_EXPERTS * CAP * D_FF];
__device__ float d_Ob [(size_t)N_EXPERTS * CAP * D_MODEL];
__device__ int   d_counts[N_EXPERTS];
__device__ int   d_tlist[N_EXPERTS * CAP];

// ---------------------------------------------------------------------------
// Helpers
// ---------------------------------------------------------------------------
__device__ __forceinline__ float gelu_f(float v) {
    return 0.5f * v * (1.0f + erff(v * 0.70710678118654752440f));
}

__device__ __forceinline__ uint32_t tf32r(float x) {
    uint32_t r;
    asm("cvt.rna.tf32.f32 %0, %1;" : "=r"(r) : "f"(x));
    return r;
}

// m16n8k8 tf32 mma: D += A(16x8 row) * B(8x8 col)
__device__ __forceinline__ void mma_tf32_16n8k8(float* c, const uint32_t* a,
                                                const uint32_t* b) {
    asm volatile(
        "mma.sync.aligned.m16n8k8.row.col.f32.tf32.tf32.f32 "
        "{%0,%1,%2,%3}, {%4,%5,%6,%7}, {%8,%9}, {%0,%1,%2,%3};"
        : "+f"(c[0]), "+f"(c[1]), "+f"(c[2]), "+f"(c[3])
        : "r"(a[0]), "r"(a[1]), "r"(a[2]), "r"(a[3]), "r"(b[0]), "r"(b[1]));
}

__device__ __forceinline__ float reduce256(float v, float* red) {
    int t = threadIdx.x;
    red[t] = v;
    __syncthreads();
    #pragma unroll
    for (int s = 128; s > 0; s >>= 1) {
        if (t < s) red[t] += red[t + s];
        __syncthreads();
    }
    float r = red[0];
    __syncthreads();
    return r;
}

__device__ __forceinline__ void tf_round(uint32_t& a, uint32_t& b, int r) {
    a += b;
    b = (b << r) | (b >> (32 - r));
    b ^= a;
}

__device__ __forceinline__ uint2 threefry2x32(uint32_t k0, uint32_t k1,
                                              uint32_t x0, uint32_t x1) {
    uint32_t ks0 = k0, ks1 = k1, ks2 = k0 ^ k1 ^ 0x1BD11BDAu;
    x0 += ks0; x1 += ks1;
    tf_round(x0, x1, 13); tf_round(x0, x1, 15); tf_round(x0, x1, 26); tf_round(x0, x1, 6);
    x0 += ks1; x1 += ks2 + 1u;
    tf_round(x0, x1, 17); tf_round(x0, x1, 29); tf_round(x0, x1, 16); tf_round(x0, x1, 24);
    x0 += ks2; x1 += ks0 + 2u;
    tf_round(x0, x1, 13); tf_round(x0, x1, 15); tf_round(x0, x1, 26); tf_round(x0, x1, 6);
    x0 += ks0; x1 += ks1 + 3u;
    tf_round(x0, x1, 17); tf_round(x0, x1, 29); tf_round(x0, x1, 16); tf_round(x0, x1, 24);
    x0 += ks1; x1 += ks2 + 4u;
    tf_round(x0, x1, 13); tf_round(x0, x1, 15); tf_round(x0, x1, 26); tf_round(x0, x1, 6);
    x0 += ks2; x1 += ks0 + 5u;
    return make_uint2(x0, x1);
}

// ---------------------------------------------------------------------------
// Kernel: zero routing counters
// ---------------------------------------------------------------------------
__global__ void zero_counts_kernel() {
    if (threadIdx.x < N_EXPERTS) d_counts[threadIdx.x] = 0;
}

// ---------------------------------------------------------------------------
// Kernel: policy head + Gumbel top-2 routing.  One block per token.
// ---------------------------------------------------------------------------
__global__ __launch_bounds__(256)
void routing_kernel(const float* __restrict__ x,
                    const float* __restrict__ pw1, const float* __restrict__ pb1,
                    const float* __restrict__ pg1, const float* __restrict__ pbb1,
                    const float* __restrict__ pw2, const float* __restrict__ pb2) {
    __shared__ float xs[D_MODEL];
    __shared__ float red[256];
    __shared__ float gbuf[D_HALF];
    __shared__ float scores[N_EXPERTS];

    int token = blockIdx.x;
    int t = threadIdx.x;

    for (int i = t; i < D_MODEL; i += 256) xs[i] = x[(size_t)token * D_MODEL + i];
    __syncthreads();

    float acc = pb1[t];
    #pragma unroll 4
    for (int k = 0; k < D_MODEL; k++)
        acc = fmaf(xs[k], pw1[k * D_HALF + t], acc);

    float mean = reduce256(acc, red) * (1.0f / D_HALF);
    float d = acc - mean;
    float var = reduce256(d * d, red) * (1.0f / D_HALF);
    float hn = d * rsqrtf(var + 1e-5f) * pg1[t] + pbb1[t];
    gbuf[t] = gelu_f(hn);
    __syncthreads();

    if (t < N_EXPERTS) {
        float lg = pb2[t];
        #pragma unroll 4
        for (int j = 0; j < D_HALF; j++)
            lg = fmaf(gbuf[j], pw2[j * N_EXPERTS + t], lg);

        // partitionable threefry: counter (0, i), bits = out0 ^ out1
        uint32_t idx = (uint32_t)(token * N_EXPERTS + t);
        uint2 r = threefry2x32(0u, 42u, 0u, idx);
        uint32_t bits = r.x ^ r.y;
        float u = __uint_as_float((bits >> 9) | 0x3f800000u) - 1.0f;
        float gn = -logf(-logf(u + 1e-10f) + 1e-10f);
        scores[t] = lg + gn;
    }
    __syncthreads();

    if (t == 0) {
        int e1 = 0; float v1 = scores[0];
        #pragma unroll
        for (int e = 1; e < N_EXPERTS; e++)
            if (scores[e] > v1) { v1 = scores[e]; e1 = e; }
        int e2 = -1; float v2 = -1e30f;
        #pragma unroll
        for (int e = 0; e < N_EXPERTS; e++) {
            if (e == e1) continue;
            if (scores[e] > v2) { v2 = scores[e]; e2 = e; }
        }
        int p = atomicAdd(&d_counts[e1], 1);
        d_tlist[e1 * CAP + p] = token;
        p = atomicAdd(&d_counts[e2], 1);
        d_tlist[e2 * CAP + p] = token;
    }
}

// ---------------------------------------------------------------------------
// Kernel: gather selected token rows
// ---------------------------------------------------------------------------
__global__ void gather_kernel(const float* __restrict__ x) {
    int m = blockIdx.x, e = blockIdx.y;
    if (m >= d_counts[e]) return;
    int token = d_tlist[e * CAP + m];
    const float4* src = (const float4*)(x + (size_t)token * D_MODEL);
    float4* dst = (float4*)(d_Xg + ((size_t)e * CAP + m) * D_MODEL);
    dst[threadIdx.x] = src[threadIdx.x];
}

// ---------------------------------------------------------------------------
// tf32 tensor-core GEMM (warp mma.sync):
//   C[e] = act(A[e] @ B[e] + bias[e]),  A: [M_e,K] rm,  B: [K,N] rm.
// Tile 128x128x32; 8 warps as 4(m) x 2(n); warp tile 32x64 = 2x8 m16n8k8.
// grid (N/128, CAP/128, N_EXPERTS), 256 threads.
// ---------------------------------------------------------------------------
#define AS_STRIDE 36
#define BS_STRIDE 136

template<int ACT>
__global__ __launch_bounds__(256)
void gemm_mma(const float* __restrict__ Aall, long strideA,
              const float* __restrict__ Ball, long strideB,
              const float* __restrict__ biasAll, long strideBias,
              float* __restrict__ Call, long strideC,
              int N, int K) {
    __shared__ uint32_t As[128 * AS_STRIDE];   // [row][k], tf32 bits
    __shared__ uint32_t Bs[32 * BS_STRIDE];    // [k][col], tf32 bits

    int e = blockIdx.z;
    int M = d_counts[e];
    int m0 = blockIdx.y * 128;
    if (m0 >= M) return;
    int n0 = blockIdx.x * 128;

    const float* A    = Aall   + (long)e * strideA;
    const float* B    = Ball   + (long)e * strideB;
    const float* bias = biasAll + (long)e * strideBias;
    float* C          = Call   + (long)e * strideC;

    int tid  = threadIdx.x;
    int wid  = tid >> 5;
    int lane = tid & 31;
    int wm = wid >> 1;            // 0..3  (m)
    int wn = wid & 1;             // 0..1  (n)
    int gid = lane >> 2;          // 0..7
    int tig = lane & 3;           // 0..3

    float acc[2][8][4];
    #pragma unroll
    for (int i = 0; i < 2; i++)
        #pragma unroll
        for (int j = 0; j < 8; j++)
            #pragma unroll
            for (int c = 0; c < 4; c++) acc[i][j][c] = 0.0f;

    for (int k0 = 0; k0 < K; k0 += 32) {
        // load A tile: 128x32 floats = 1024 float4, 4 per thread
        #pragma unroll
        for (int i = 0; i < 4; i++) {
            int idx = i * 256 + tid;
            int r = idx >> 3, c4 = (idx & 7) << 2;
            float4 v = make_float4(0.f, 0.f, 0.f, 0.f);
            if (m0 + r < M)
                v = *(const float4*)&A[(long)(m0 + r) * K + k0 + c4];
            uint32_t* dst = &As[r * AS_STRIDE + c4];
            dst[0] = tf32r(v.x); dst[1] = tf32r(v.y);
            dst[2] = tf32r(v.z); dst[3] = tf32r(v.w);
        }
        // load B tile: 32x128 floats
        #pragma unroll
        for (int i = 0; i < 4; i++) {
            int idx = i * 256 + tid;
            int r = idx >> 5, c4 = (idx & 31) << 2;
            float4 v = *(const float4*)&B[(long)(k0 + r) * N + n0 + c4];
            uint32_t* dst = &Bs[r * BS_STRIDE + c4];
            dst[0] = tf32r(v.x); dst[1] = tf32r(v.y);
            dst[2] = tf32r(v.z); dst[3] = tf32r(v.w);
        }
        __syncthreads();

        #pragma unroll
        for (int ks = 0; ks < 4; ks++) {
            int kk = ks * 8;
            uint32_t a[2][4];
            #pragma unroll
            for (int mt = 0; mt < 2; mt++) {
                int row = wm * 32 + mt * 16 + gid;
                const uint32_t* ap = &As[row * AS_STRIDE + kk + tig];
                a[mt][0] = ap[0];
                a[mt][1] = ap[8 * AS_STRIDE];
                a[mt][2] = ap[4];
                a[mt][3] = ap[8 * AS_STRIDE + 4];
            }
            #pragma unroll
            for (int nt = 0; nt < 8; nt++) {
                int col = wn * 64 + nt * 8 + gid;
                uint32_t b[2];
                b[0] = Bs[(kk + tig) * BS_STRIDE + col];
                b[1] = Bs[(kk + tig + 4) * BS_STRIDE + col];
                mma_tf32_16n8k8(acc[0][nt], a[0], b);
                mma_tf32_16n8k8(acc[1][nt], a[1], b);
            }
        }
        __syncthreads();
    }

    // epilogue: bias + act, float2 stores
    #pragma unroll
    for (int mt = 0; mt < 2; mt++) {
        #pragma unroll
        for (int nt = 0; nt < 8; nt++) {
            int col = n0 + wn * 64 + nt * 8 + 2 * tig;
            float b0 = bias[col], b1 = bias[col + 1];
            int r0 = m0 + wm * 32 + mt * 16 + gid;
            int r1 = r0 + 8;
            if (r0 < M) {
                float v0 = acc[mt][nt][0] + b0;
                float v1 = acc[mt][nt][1] + b1;
                if (ACT == 1) { v0 = gelu_f(v0); v1 = gelu_f(v1); }
                *(float2*)&C[(long)r0 * N + col] = make_float2(v0, v1);
            }
            if (r1 < M) {
                float v0 = acc[mt][nt][2] + b0;
                float v1 = acc[mt][nt][3] + b1;
                if (ACT == 1) { v0 = gelu_f(v0); v1 = gelu_f(v1); }
                *(float2*)&C[(long)r1 * N + col] = make_float2(v0, v1);
            }
        }
    }
}

// ---------------------------------------------------------------------------
// Kernel: per-row LN of h2, sigmoid gate from h, residual update.
// ---------------------------------------------------------------------------
__global__ __launch_bounds__(256)
void lngate_kernel(const float* __restrict__ ng, const float* __restrict__ nb,
                   const float* __restrict__ gwv) {
    __shared__ float red[256];
    int m = blockIdx.x, e = blockIdx.y;
    if (m >= d_counts[e]) return;
    int t = threadIdx.x;

    float* h = d_H + ((size_t)e * CAP + m) * D_FF;
    const float* h2 = d_H2 + ((size_t)e * CAP + m) * D_FF;
    const float* ng_e = ng + (size_t)e * (N_LAYERS * D_FF);
    const float* nb_e = nb + (size_t)e * (N_LAYERS * D_FF);
    const float* gw_e = gwv + (size_t)e * (N_LAYERS * D_FF);

    float hv[4], h2v[4];
    float s = 0.f, sq = 0.f, dot = 0.f;
    #pragma unroll
    for (int c = 0; c < 4; c++) {
        int i = t + c * 256;
        hv[c] = h[i];
        h2v[c] = h2[i];
        s += h2v[c];
        dot = fmaf(hv[c], gw_e[i], dot);
    }
    float mean = reduce256(s, red) * (1.0f / D_FF);
    #pragma unroll
    for (int c = 0; c < 4; c++) { float d = h2v[c] - mean; sq += d * d; }
    float var = reduce256(sq, red) * (1.0f / D_FF);
    float dtot = reduce256(dot, red);
    float gate = 1.0f / (1.0f + expf(-dtot));
    float rstd = rsqrtf(var + 1e-5f);

    #pragma unroll
    for (int c = 0; c < 4; c++) {
        int i = t + c * 256;
        float hn = (h2v[c] - mean) * rstd * ng_e[i] + nb_e[i];
        h[i] = hv[c] + gate * hn;
    }
}

// ---------------------------------------------------------------------------
// Kernel: final residual LN + scatter-add into output.
// ---------------------------------------------------------------------------
__global__ __launch_bounds__(256)
void final_kernel(const float* __restrict__ x,
                  const float* __restrict__ fng, const float* __restrict__ fnb,
                  float* __restrict__ out) {
    __shared__ float red[256];
    int m = blockIdx.x, e = blockIdx.y;
    if (m >= d_counts[e]) return;
    int t = threadIdx.x;
    int token = d_tlist[e * CAP + m];

    const float* orow = d_Ob + ((size_t)e * CAP + m) * D_MODEL;
    const float* xrow = x + (size_t)token * D_MODEL;
    const float* g = fng + (size_t)e * D_MODEL;
    const float* b = fnb + (size_t)e * D_MODEL;

    float v[2];
    float s = 0.f, sq = 0.f;
    #pragma unroll
    for (int c = 0; c < 2; c++) {
        int i = t + c * 256;
        v[c] = xrow[i] + orow[i];
        s += v[c];
    }
    float mean = reduce256(s, red) * (1.0f / D_MODEL);
    #pragma unroll
    for (int c = 0; c < 2; c++) { float d = v[c] - mean; sq += d * d; }
    float var = reduce256(sq, red) * (1.0f / D_MODEL);
    float rstd = rsqrtf(var + 1e-5f);

    #pragma unroll
    for (int c = 0; c < 2; c++) {
        int i = t + c * 256;
        float y = (v[c] - mean) * rstd * g[i] + b[i];
        atomicAdd(&out[(size_t)token * D_MODEL + i], y);
    }
}

// ---------------------------------------------------------------------------
// Launch
// ---------------------------------------------------------------------------
extern "C" void kernel_launch(void* const* d_in, const int* in_sizes, int n_in,
                              void* d_out, int out_size) {
    const float* x    = (const float*)d_in[0];
    const float* pw1  = (const float*)d_in[1];
    const float* pb1  = (const float*)d_in[2];
    const float* pg1  = (const float*)d_in[3];
    const float* pbb1 = (const float*)d_in[4];
    const float* pw2  = (const float*)d_in[5];
    const float* pb2  = (const float*)d_in[6];
    const float* Win  = (const float*)d_in[7];
    const float* b_in = (const float*)d_in[8];
    const float* W1   = (const float*)d_in[9];
    const float* b1   = (const float*)d_in[10];
    const float* W2   = (const float*)d_in[11];
    const float* b2   = (const float*)d_in[12];
    const float* ng   = (const float*)d_in[13];
    const float* nb   = (const float*)d_in[14];
    const float* gw   = (const float*)d_in[15];
    const float* Wout = (const float*)d_in[16];
    const float* bout = (const float*)d_in[17];
    const float* fng  = (const float*)d_in[18];
    const float* fnb  = (const float*)d_in[19];
    float* out = (float*)d_out;

    float *Xg, *H, *A2, *H2, *Ob;
    cudaGetSymbolAddress((void**)&Xg, d_Xg);
    cudaGetSymbolAddress((void**)&H,  d_H);
    cudaGetSymbolAddress((void**)&A2, d_A2);
    cudaGetSymbolAddress((void**)&H2, d_H2);
    cudaGetSymbolAddress((void**)&Ob, d_Ob);

    cudaMemsetAsync(out, 0, (size_t)out_size * sizeof(float), 0);
    zero_counts_kernel<<<1, 32>>>();
    routing_kernel<<<N_TOKENS, 256>>>(x, pw1, pb1, pg1, pbb1, pw2, pb2);
    gather_kernel<<<dim3(CAP, N_EXPERTS), 128>>>(x);

    // H = Xg @ Win + b_in                  [M,512] x [512,1024]
    gemm_mma<0><<<dim3(D_FF / 128, CAP / 128, N_EXPERTS), 256>>>(
        Xg, (long)CAP * D_MODEL,
        Win, (long)D_MODEL * D_FF,
        b_in, (long)D_FF,
        H, (long)CAP * D_FF,
        D_FF, D_MODEL);

    for (int l = 0; l < N_LAYERS; l++) {
        // A2 = gelu(H @ W1[l] + b1[l])     [M,1024] x [1024,2048]
        gemm_mma<1><<<dim3(D_FF2 / 128, CAP / 128, N_EXPERTS), 256>>>(
            H, (long)CAP * D_FF,
            W1 + (long)l * D_FF * D_FF2, (long)N_LAYERS * D_FF * D_FF2,
            b1 + (long)l * D_FF2, (long)N_LAYERS * D_FF2,
            A2, (long)CAP * D_FF2,
            D_FF2, D_FF);
        // H2 = A2 @ W2[l] + b2[l]          [M,2048] x [2048,1024]
        gemm_mma<0><<<dim3(D_FF / 128, CAP / 128, N_EXPERTS), 256>>>(
            A2, (long)CAP * D_FF2,
            W2 + (long)l * D_FF2 * D_FF, (long)N_LAYERS * D_FF2 * D_FF,
            b2 + (long)l * D_FF, (long)N_LAYERS * D_FF,
            H2, (long)CAP * D_FF,
            D_FF, D_FF2);
        lngate_kernel<<<dim3(CAP, N_EXPERTS), 256>>>(
            ng + (long)l * D_FF, nb + (long)l * D_FF, gw + (long)l * D_FF);
    }

    // Ob = H @ Wout + bout                 [M,1024] x [1024,512]
    gemm_mma<0><<<dim3(D_MODEL / 128, CAP / 128, N_EXPERTS), 256>>>(
        H, (long)CAP * D_FF,
        Wout, (long)D_FF * D_MODEL,
        bout, (long)D_MODEL,
        Ob, (long)CAP * D_MODEL,
        D_MODEL, D_FF);

    final_kernel<<<dim3(CAP, N_EXPERTS), 256>>>(x, fng, fnb, out);
}

// round 10
// speedup vs baseline: 3.3214x; 1.0996x over previous
#include <cuda_runtime.h>
#include <cuda_bf16.h>
#include <cstdint>

// ---------------------------------------------------------------------------
// Problem constants
// ---------------------------------------------------------------------------
#define D_MODEL   512
#define D_HALF    256
#define D_FF      1024
#define D_FF2     2048
#define N_LAYERS  2
#define N_EXPERTS 8
#define N_TOKENS  2048
#define CAP       2048

// GEMM smem staging
#define AS_STRIDE 36
#define BS_STRIDE 136
#define A_WORDS   (128 * AS_STRIDE)          // 4608
#define B_WORDS   (32 * BS_STRIDE)           // 4352
#define STAGE_WORDS (A_WORDS + B_WORDS)      // 8960
#define NSTAGE    3
#define GEMM_SMEM (STAGE_WORDS * NSTAGE * 4) // 107520 bytes

// ---------------------------------------------------------------------------
// Static scratch (no allocations allowed)
// ---------------------------------------------------------------------------
__device__ float d_Xg [(size_t)N_EXPERTS * CAP * D_MODEL];
__device__ float d_H  [(size_t)N_EXPERTS * CAP * D_FF];
__device__ float d_A2 [(size_t)N_EXPERTS * CAP * D_FF2];
__device__ float d_H2 [(size_t)N_EXPERTS * CAP * D_FF];
__device__ float d_Ob [(size_t)N_EXPERTS * CAP * D_MODEL];
__device__ int   d_counts[N_EXPERTS];
__device__ int   d_tlist[N_EXPERTS * CAP];

// ---------------------------------------------------------------------------
// Helpers
// ---------------------------------------------------------------------------
__device__ __forceinline__ float gelu_f(float v) {
    return 0.5f * v * (1.0f + erff(v * 0.70710678118654752440f));
}

__device__ __forceinline__ uint32_t smem_u32(const void* p) {
    uint32_t a;
    asm("{ .reg .u64 t; cvta.to.shared.u64 t, %1; cvt.u32.u64 %0, t; }" : "=r"(a) : "l"(p));
    return a;
}

__device__ __forceinline__ void cp16(uint32_t dst, const void* src, int szbytes) {
    asm volatile("cp.async.cg.shared.global [%0], [%1], 16, %2;"
                 :: "r"(dst), "l"(src), "r"(szbytes));
}
__device__ __forceinline__ void cp16f(uint32_t dst, const void* src) {
    asm volatile("cp.async.cg.shared.global [%0], [%1], 16;"
                 :: "r"(dst), "l"(src));
}
__device__ __forceinline__ void cp_commit() {
    asm volatile("cp.async.commit_group;" ::: "memory");
}
template<int N>
__device__ __forceinline__ void cp_wait() {
    asm volatile("cp.async.wait_group %0;" :: "n"(N) : "memory");
}

// m16n8k8 tf32 mma: D += A(16x8 row) * B(8x8 col)
__device__ __forceinline__ void mma_tf32_16n8k8(float* c, const uint32_t* a,
                                                const uint32_t* b) {
    asm volatile(
        "mma.sync.aligned.m16n8k8.row.col.f32.tf32.tf32.f32 "
        "{%0,%1,%2,%3}, {%4,%5,%6,%7}, {%8,%9}, {%0,%1,%2,%3};"
        : "+f"(c[0]), "+f"(c[1]), "+f"(c[2]), "+f"(c[3])
        : "r"(a[0]), "r"(a[1]), "r"(a[2]), "r"(a[3]), "r"(b[0]), "r"(b[1]));
}

__device__ __forceinline__ float reduce256(float v, float* red) {
    int t = threadIdx.x;
    red[t] = v;
    __syncthreads();
    #pragma unroll
    for (int s = 128; s > 0; s >>= 1) {
        if (t < s) red[t] += red[t + s];
        __syncthreads();
    }
    float r = red[0];
    __syncthreads();
    return r;
}

__device__ __forceinline__ void tf_round(uint32_t& a, uint32_t& b, int r) {
    a += b;
    b = (b << r) | (b >> (32 - r));
    b ^= a;
}

__device__ __forceinline__ uint2 threefry2x32(uint32_t k0, uint32_t k1,
                                              uint32_t x0, uint32_t x1) {
    uint32_t ks0 = k0, ks1 = k1, ks2 = k0 ^ k1 ^ 0x1BD11BDAu;
    x0 += ks0; x1 += ks1;
    tf_round(x0, x1, 13); tf_round(x0, x1, 15); tf_round(x0, x1, 26); tf_round(x0, x1, 6);
    x0 += ks1; x1 += ks2 + 1u;
    tf_round(x0, x1, 17); tf_round(x0, x1, 29); tf_round(x0, x1, 16); tf_round(x0, x1, 24);
    x0 += ks2; x1 += ks0 + 2u;
    tf_round(x0, x1, 13); tf_round(x0, x1, 15); tf_round(x0, x1, 26); tf_round(x0, x1, 6);
    x0 += ks0; x1 += ks1 + 3u;
    tf_round(x0, x1, 17); tf_round(x0, x1, 29); tf_round(x0, x1, 16); tf_round(x0, x1, 24);
    x0 += ks1; x1 += ks2 + 4u;
    tf_round(x0, x1, 13); tf_round(x0, x1, 15); tf_round(x0, x1, 26); tf_round(x0, x1, 6);
    x0 += ks2; x1 += ks0 + 5u;
    return make_uint2(x0, x1);
}

// ---------------------------------------------------------------------------
// Kernel: zero routing counters
// ---------------------------------------------------------------------------
__global__ void zero_counts_kernel() {
    if (threadIdx.x < N_EXPERTS) d_counts[threadIdx.x] = 0;
}

// ---------------------------------------------------------------------------
// Kernel: policy head + Gumbel top-2 routing.  One block per token.
// ---------------------------------------------------------------------------
__global__ __launch_bounds__(256)
void routing_kernel(const float* __restrict__ x,
                    const float* __restrict__ pw1, const float* __restrict__ pb1,
                    const float* __restrict__ pg1, const float* __restrict__ pbb1,
                    const float* __restrict__ pw2, const float* __restrict__ pb2) {
    __shared__ float xs[D_MODEL];
    __shared__ float red[256];
    __shared__ float gbuf[D_HALF];
    __shared__ float scores[N_EXPERTS];

    int token = blockIdx.x;
    int t = threadIdx.x;

    for (int i = t; i < D_MODEL; i += 256) xs[i] = x[(size_t)token * D_MODEL + i];
    __syncthreads();

    float acc = pb1[t];
    #pragma unroll 4
    for (int k = 0; k < D_MODEL; k++)
        acc = fmaf(xs[k], pw1[k * D_HALF + t], acc);

    float mean = reduce256(acc, red) * (1.0f / D_HALF);
    float d = acc - mean;
    float var = reduce256(d * d, red) * (1.0f / D_HALF);
    float hn = d * rsqrtf(var + 1e-5f) * pg1[t] + pbb1[t];
    gbuf[t] = gelu_f(hn);
    __syncthreads();

    if (t < N_EXPERTS) {
        float lg = pb2[t];
        #pragma unroll 4
        for (int j = 0; j < D_HALF; j++)
            lg = fmaf(gbuf[j], pw2[j * N_EXPERTS + t], lg);

        // partitionable threefry: counter (0, i), bits = out0 ^ out1
        uint32_t idx = (uint32_t)(token * N_EXPERTS + t);
        uint2 r = threefry2x32(0u, 42u, 0u, idx);
        uint32_t bits = r.x ^ r.y;
        float u = __uint_as_float((bits >> 9) | 0x3f800000u) - 1.0f;
        float gn = -logf(-logf(u + 1e-10f) + 1e-10f);
        scores[t] = lg + gn;
    }
    __syncthreads();

    if (t == 0) {
        int e1 = 0; float v1 = scores[0];
        #pragma unroll
        for (int e = 1; e < N_EXPERTS; e++)
            if (scores[e] > v1) { v1 = scores[e]; e1 = e; }
        int e2 = -1; float v2 = -1e30f;
        #pragma unroll
        for (int e = 0; e < N_EXPERTS; e++) {
            if (e == e1) continue;
            if (scores[e] > v2) { v2 = scores[e]; e2 = e; }
        }
        int p = atomicAdd(&d_counts[e1], 1);
        d_tlist[e1 * CAP + p] = token;
        p = atomicAdd(&d_counts[e2], 1);
        d_tlist[e2 * CAP + p] = token;
    }
}

// ---------------------------------------------------------------------------
// Kernel: gather selected token rows
// ---------------------------------------------------------------------------
__global__ void gather_kernel(const float* __restrict__ x) {
    int m = blockIdx.x, e = blockIdx.y;
    if (m >= d_counts[e]) return;
    int token = d_tlist[e * CAP + m];
    const float4* src = (const float4*)(x + (size_t)token * D_MODEL);
    float4* dst = (float4*)(d_Xg + ((size_t)e * CAP + m) * D_MODEL);
    dst[threadIdx.x] = src[threadIdx.x];
}

// ---------------------------------------------------------------------------
// tf32 tensor-core GEMM, cp.async 3-stage pipeline:
//   C[e] = act(A[e] @ B[e] + bias[e]),  A: [M_e,K] rm,  B: [K,N] rm.
// Tile 128x128x32; 8 warps as 4(m) x 2(n); warp tile 32x64 = 2x8 m16n8k8.
// grid (N/128, CAP/128, N_EXPERTS), 256 threads, dyn smem = GEMM_SMEM.
// fp32 bits are fed to mma.tf32 directly (HW truncates mantissa; the
// resulting ~2e-4 scale bias is absorbed by downstream LayerNorms).
// ---------------------------------------------------------------------------
template<int ACT>
__global__ __launch_bounds__(256)
void gemm_mma(const float* __restrict__ Aall, long strideA,
              const float* __restrict__ Ball, long strideB,
              const float* __restrict__ biasAll, long strideBias,
              float* __restrict__ Call, long strideC,
              int N, int K) {
    extern __shared__ uint32_t sm[];

    int e = blockIdx.z;
    int M = d_counts[e];
    int m0 = blockIdx.y * 128;
    if (m0 >= M) return;
    int n0 = blockIdx.x * 128;

    const float* A    = Aall   + (long)e * strideA;
    const float* B    = Ball   + (long)e * strideB;
    const float* bias = biasAll + (long)e * strideBias;
    float* C          = Call   + (long)e * strideC;

    int tid  = threadIdx.x;
    int wid  = tid >> 5;
    int lane = tid & 31;
    int wm = wid >> 1;            // 0..3  (m)
    int wn = wid & 1;             // 0..1  (n)
    int gid = lane >> 2;          // 0..7
    int tig = lane & 3;           // 0..3

    // precomputed copy indices
    int ar = tid >> 1;                    // rows 0..127 (2 thr/row)
    int ac4 = (tid & 1) << 4;             // col 0 or 16 -> wait, 8 cols of 4
    // A: 128 rows x 32 cols = 1024 float4; idx = i*256+tid; r=idx>>3, c=(idx&7)*4
    // B: 32 rows x 128 cols = 1024 float4; r=idx>>5, c=(idx&31)*4
    (void)ar; (void)ac4;

    float acc[2][8][4];
    #pragma unroll
    for (int i = 0; i < 2; i++)
        #pragma unroll
        for (int j = 0; j < 8; j++)
            #pragma unroll
            for (int c = 0; c < 4; c++) acc[i][j][c] = 0.0f;

    const int NC = K >> 5;

    // tile loader
    auto load_tile = [&](int chunk, int buf) {
        uint32_t* As = sm + buf * STAGE_WORDS;
        uint32_t* Bs = As + A_WORDS;
        int k0 = chunk << 5;
        #pragma unroll
        for (int i = 0; i < 4; i++) {
            int idx = i * 256 + tid;
            int r = idx >> 3, c4 = (idx & 7) << 2;
            int rr = m0 + r;
            int sz = (rr < M) ? 16 : 0;
            int rc = (rr < M) ? rr : 0;
            cp16(smem_u32(&As[r * AS_STRIDE + c4]),
                 &A[(long)rc * K + k0 + c4], sz);
        }
        #pragma unroll
        for (int i = 0; i < 4; i++) {
            int idx = i * 256 + tid;
            int r = idx >> 5, c4 = (idx & 31) << 2;
            cp16f(smem_u32(&Bs[r * BS_STRIDE + c4]),
                  &B[(long)(k0 + r) * N + n0 + c4]);
        }
        cp_commit();
    };

    load_tile(0, 0);
    load_tile(1, 1);

    for (int chunk = 0; chunk < NC; chunk++) {
        if (chunk + 1 < NC) cp_wait<1>();
        else                cp_wait<0>();
        __syncthreads();
        if (chunk + 2 < NC) load_tile(chunk + 2, (chunk + 2) % NSTAGE);

        uint32_t* As = sm + (chunk % NSTAGE) * STAGE_WORDS;
        uint32_t* Bs = As + A_WORDS;

        #pragma unroll
        for (int ks = 0; ks < 4; ks++) {
            int kk = ks * 8;
            uint32_t a[2][4];
            #pragma unroll
            for (int mt = 0; mt < 2; mt++) {
                int row = wm * 32 + mt * 16 + gid;
                const uint32_t* ap = &As[row * AS_STRIDE + kk + tig];
                a[mt][0] = ap[0];
                a[mt][1] = ap[8 * AS_STRIDE];
                a[mt][2] = ap[4];
                a[mt][3] = ap[8 * AS_STRIDE + 4];
            }
            #pragma unroll
            for (int nt = 0; nt < 8; nt++) {
                int col = wn * 64 + nt * 8 + gid;
                uint32_t b[2];
                b[0] = Bs[(kk + tig) * BS_STRIDE + col];
                b[1] = Bs[(kk + tig + 4) * BS_STRIDE + col];
                mma_tf32_16n8k8(acc[0][nt], a[0], b);
                mma_tf32_16n8k8(acc[1][nt], a[1], b);
            }
        }
    }

    // epilogue: bias + act, float2 stores
    #pragma unroll
    for (int mt = 0; mt < 2; mt++) {
        #pragma unroll
        for (int nt = 0; nt < 8; nt++) {
            int col = n0 + wn * 64 + nt * 8 + 2 * tig;
            float b0 = bias[col], b1 = bias[col + 1];
            int r0 = m0 + wm * 32 + mt * 16 + gid;
            int r1 = r0 + 8;
            if (r0 < M) {
                float v0 = acc[mt][nt][0] + b0;
                float v1 = acc[mt][nt][1] + b1;
                if (ACT == 1) { v0 = gelu_f(v0); v1 = gelu_f(v1); }
                *(float2*)&C[(long)r0 * N + col] = make_float2(v0, v1);
            }
            if (r1 < M) {
                float v0 = acc[mt][nt][2] + b0;
                float v1 = acc[mt][nt][3] + b1;
                if (ACT == 1) { v0 = gelu_f(v0); v1 = gelu_f(v1); }
                *(float2*)&C[(long)r1 * N + col] = make_float2(v0, v1);
            }
        }
    }
}

// ---------------------------------------------------------------------------
// Kernel: per-row LN of h2, sigmoid gate from h, residual update.
// ---------------------------------------------------------------------------
__global__ __launch_bounds__(256)
void lngate_kernel(const float* __restrict__ ng, const float* __restrict__ nb,
                   const float* __restrict__ gwv) {
    __shared__ float red[256];
    int m = blockIdx.x, e = blockIdx.y;
    if (m >= d_counts[e]) return;
    int t = threadIdx.x;

    float* h = d_H + ((size_t)e * CAP + m) * D_FF;
    const float* h2 = d_H2 + ((size_t)e * CAP + m) * D_FF;
    const float* ng_e = ng + (size_t)e * (N_LAYERS * D_FF);
    const float* nb_e = nb + (size_t)e * (N_LAYERS * D_FF);
    const float* gw_e = gwv + (size_t)e * (N_LAYERS * D_FF);

    float hv[4], h2v[4];
    float s = 0.f, sq = 0.f, dot = 0.f;
    #pragma unroll
    for (int c = 0; c < 4; c++) {
        int i = t + c * 256;
        hv[c] = h[i];
        h2v[c] = h2[i];
        s += h2v[c];
        dot = fmaf(hv[c], gw_e[i], dot);
    }
    float mean = reduce256(s, red) * (1.0f / D_FF);
    #pragma unroll
    for (int c = 0; c < 4; c++) { float d = h2v[c] - mean; sq += d * d; }
    float var = reduce256(sq, red) * (1.0f / D_FF);
    float dtot = reduce256(dot, red);
    float gate = 1.0f / (1.0f + expf(-dtot));
    float rstd = rsqrtf(var + 1e-5f);

    #pragma unroll
    for (int c = 0; c < 4; c++) {
        int i = t + c * 256;
        float hn = (h2v[c] - mean) * rstd * ng_e[i] + nb_e[i];
        h[i] = hv[c] + gate * hn;
    }
}

// ---------------------------------------------------------------------------
// Kernel: final residual LN + scatter-add into output.
// ---------------------------------------------------------------------------
__global__ __launch_bounds__(256)
void final_kernel(const float* __restrict__ x,
                  const float* __restrict__ fng, const float* __restrict__ fnb,
                  float* __restrict__ out) {
    __shared__ float red[256];
    int m = blockIdx.x, e = blockIdx.y;
    if (m >= d_counts[e]) return;
    int t = threadIdx.x;
    int token = d_tlist[e * CAP + m];

    const float* orow = d_Ob + ((size_t)e * CAP + m) * D_MODEL;
    const float* xrow = x + (size_t)token * D_MODEL;
    const float* g = fng + (size_t)e * D_MODEL;
    const float* b = fnb + (size_t)e * D_MODEL;

    float v[2];
    float s = 0.f, sq = 0.f;
    #pragma unroll
    for (int c = 0; c < 2; c++) {
        int i = t + c * 256;
        v[c] = xrow[i] + orow[i];
        s += v[c];
    }
    float mean = reduce256(s, red) * (1.0f / D_MODEL);
    #pragma unroll
    for (int c = 0; c < 2; c++) { float d = v[c] - mean; sq += d * d; }
    float var = reduce256(sq, red) * (1.0f / D_MODEL);
    float rstd = rsqrtf(var + 1e-5f);

    #pragma unroll
    for (int c = 0; c < 2; c++) {
        int i = t + c * 256;
        float y = (v[c] - mean) * rstd * g[i] + b[i];
        atomicAdd(&out[(size_t)token * D_MODEL + i], y);
    }
}

// ---------------------------------------------------------------------------
// Launch
// ---------------------------------------------------------------------------
extern "C" void kernel_launch(void* const* d_in, const int* in_sizes, int n_in,
                              void* d_out, int out_size) {
    const float* x    = (const float*)d_in[0];
    const float* pw1  = (const float*)d_in[1];
    const float* pb1  = (const float*)d_in[2];
    const float* pg1  = (const float*)d_in[3];
    const float* pbb1 = (const float*)d_in[4];
    const float* pw2  = (const float*)d_in[5];
    const float* pb2  = (const float*)d_in[6];
    const float* Win  = (const float*)d_in[7];
    const float* b_in = (const float*)d_in[8];
    const float* W1   = (const float*)d_in[9];
    const float* b1   = (const float*)d_in[10];
    const float* W2   = (const float*)d_in[11];
    const float* b2   = (const float*)d_in[12];
    const float* ng   = (const float*)d_in[13];
    const float* nb   = (const float*)d_in[14];
    const float* gw   = (const float*)d_in[15];
    const float* Wout = (const float*)d_in[16];
    const float* bout = (const float*)d_in[17];
    const float* fng  = (const float*)d_in[18];
    const float* fnb  = (const float*)d_in[19];
    float* out = (float*)d_out;

    float *Xg, *H, *A2, *H2, *Ob;
    cudaGetSymbolAddress((void**)&Xg, d_Xg);
    cudaGetSymbolAddress((void**)&H,  d_H);
    cudaGetSymbolAddress((void**)&A2, d_A2);
    cudaGetSymbolAddress((void**)&H2, d_H2);
    cudaGetSymbolAddress((void**)&Ob, d_Ob);

    cudaFuncSetAttribute(gemm_mma<0>, cudaFuncAttributeMaxDynamicSharedMemorySize, GEMM_SMEM);
    cudaFuncSetAttribute(gemm_mma<1>, cudaFuncAttributeMaxDynamicSharedMemorySize, GEMM_SMEM);

    cudaMemsetAsync(out, 0, (size_t)out_size * sizeof(float), 0);
    zero_counts_kernel<<<1, 32>>>();
    routing_kernel<<<N_TOKENS, 256>>>(x, pw1, pb1, pg1, pbb1, pw2, pb2);
    gather_kernel<<<dim3(CAP, N_EXPERTS), 128>>>(x);

    // H = Xg @ Win + b_in                  [M,512] x [512,1024]
    gemm_mma<0><<<dim3(D_FF / 128, CAP / 128, N_EXPERTS), 256, GEMM_SMEM>>>(
        Xg, (long)CAP * D_MODEL,
        Win, (long)D_MODEL * D_FF,
        b_in, (long)D_FF,
        H, (long)CAP * D_FF,
        D_FF, D_MODEL);

    for (int l = 0; l < N_LAYERS; l++) {
        // A2 = gelu(H @ W1[l] + b1[l])     [M,1024] x [1024,2048]
        gemm_mma<1><<<dim3(D_FF2 / 128, CAP / 128, N_EXPERTS), 256, GEMM_SMEM>>>(
            H, (long)CAP * D_FF,
            W1 + (long)l * D_FF * D_FF2, (long)N_LAYERS * D_FF * D_FF2,
            b1 + (long)l * D_FF2, (long)N_LAYERS * D_FF2,
            A2, (long)CAP * D_FF2,
            D_FF2, D_FF);
        // H2 = A2 @ W2[l] + b2[l]          [M,2048] x [2048,1024]
        gemm_mma<0><<<dim3(D_FF / 128, CAP / 128, N_EXPERTS), 256, GEMM_SMEM>>>(
            A2, (long)CAP * D_FF2,
            W2 + (long)l * D_FF2 * D_FF, (long)N_LAYERS * D_FF2 * D_FF,
            b2 + (long)l * D_FF, (long)N_LAYERS * D_FF,
            H2, (long)CAP * D_FF,
            D_FF, D_FF2);
        lngate_kernel<<<dim3(CAP, N_EXPERTS), 256>>>(
            ng + (long)l * D_FF, nb + (long)l * D_FF, gw + (long)l * D_FF);
    }

    // Ob = H @ Wout + bout                 [M,1024] x [1024,512]
    gemm_mma<0><<<dim3(D_MODEL / 128, CAP / 128, N_EXPERTS), 256, GEMM_SMEM>>>(
        H, (long)CAP * D_FF,
        Wout, (long)D_FF * D_MODEL,
        bout, (long)D_MODEL,
        Ob, (long)CAP * D_MODEL,
        D_MODEL, D_FF);

    final_kernel<<<dim3(CAP, N_EXPERTS), 256>>>(x, fng, fnb, out);
}

// round 11
// speedup vs baseline: 3.3798x; 1.0176x over previous
#include <cuda_runtime.h>
#include <cuda_bf16.h>
#include <cstdint>

// ---------------------------------------------------------------------------
// Problem constants
// ---------------------------------------------------------------------------
#define D_MODEL   512
#define D_HALF    256
#define D_FF      1024
#define D_FF2     2048
#define N_LAYERS  2
#define N_EXPERTS 8
#define N_TOKENS  2048
#define CAP       2048

// GEMM smem staging
#define AS_STRIDE 36
#define BS_STRIDE 136
#define A_WORDS   (128 * AS_STRIDE)          // 4608
#define B_WORDS   (32 * BS_STRIDE)           // 4352
#define STAGE_WORDS (A_WORDS + B_WORDS)      // 8960
#define NSTAGE    2
#define GEMM_SMEM (STAGE_WORDS * NSTAGE * 4) // 71680 bytes -> 2 CTAs/SM

// ---------------------------------------------------------------------------
// Static scratch (no allocations allowed)
// ---------------------------------------------------------------------------
__device__ float d_Xg [(size_t)N_EXPERTS * CAP * D_MODEL];
__device__ float d_H  [(size_t)N_EXPERTS * CAP * D_FF];
__device__ float d_A2 [(size_t)N_EXPERTS * CAP * D_FF2];
__device__ float d_H2 [(size_t)N_EXPERTS * CAP * D_FF];
__device__ float d_Ob [(size_t)N_EXPERTS * CAP * D_MODEL];
__device__ int   d_counts[N_EXPERTS];
__device__ int   d_tlist[N_EXPERTS * CAP];

// ---------------------------------------------------------------------------
// Helpers
// ---------------------------------------------------------------------------
__device__ __forceinline__ float gelu_f(float v) {
    return 0.5f * v * (1.0f + erff(v * 0.70710678118654752440f));
}

__device__ __forceinline__ uint32_t smem_u32(const void* p) {
    uint32_t a;
    asm("{ .reg .u64 t; cvta.to.shared.u64 t, %1; cvt.u32.u64 %0, t; }" : "=r"(a) : "l"(p));
    return a;
}

__device__ __forceinline__ void cp16(uint32_t dst, const void* src, int szbytes) {
    asm volatile("cp.async.cg.shared.global [%0], [%1], 16, %2;"
                 :: "r"(dst), "l"(src), "r"(szbytes));
}
__device__ __forceinline__ void cp16f(uint32_t dst, const void* src) {
    asm volatile("cp.async.cg.shared.global [%0], [%1], 16;"
                 :: "r"(dst), "l"(src));
}
__device__ __forceinline__ void cp_commit() {
    asm volatile("cp.async.commit_group;" ::: "memory");
}
template<int N>
__device__ __forceinline__ void cp_wait() {
    asm volatile("cp.async.wait_group %0;" :: "n"(N) : "memory");
}

// m16n8k8 tf32 mma: D += A(16x8 row) * B(8x8 col)
__device__ __forceinline__ void mma_tf32_16n8k8(float* c, const uint32_t* a,
                                                const uint32_t* b) {
    asm volatile(
        "mma.sync.aligned.m16n8k8.row.col.f32.tf32.tf32.f32 "
        "{%0,%1,%2,%3}, {%4,%5,%6,%7}, {%8,%9}, {%0,%1,%2,%3};"
        : "+f"(c[0]), "+f"(c[1]), "+f"(c[2]), "+f"(c[3])
        : "r"(a[0]), "r"(a[1]), "r"(a[2]), "r"(a[3]), "r"(b[0]), "r"(b[1]));
}

__device__ __forceinline__ float reduce256(float v, float* red) {
    int t = threadIdx.x;
    red[t] = v;
    __syncthreads();
    #pragma unroll
    for (int s = 128; s > 0; s >>= 1) {
        if (t < s) red[t] += red[t + s];
        __syncthreads();
    }
    float r = red[0];
    __syncthreads();
    return r;
}

__device__ __forceinline__ void tf_round(uint32_t& a, uint32_t& b, int r) {
    a += b;
    b = (b << r) | (b >> (32 - r));
    b ^= a;
}

__device__ __forceinline__ uint2 threefry2x32(uint32_t k0, uint32_t k1,
                                              uint32_t x0, uint32_t x1) {
    uint32_t ks0 = k0, ks1 = k1, ks2 = k0 ^ k1 ^ 0x1BD11BDAu;
    x0 += ks0; x1 += ks1;
    tf_round(x0, x1, 13); tf_round(x0, x1, 15); tf_round(x0, x1, 26); tf_round(x0, x1, 6);
    x0 += ks1; x1 += ks2 + 1u;
    tf_round(x0, x1, 17); tf_round(x0, x1, 29); tf_round(x0, x1, 16); tf_round(x0, x1, 24);
    x0 += ks2; x1 += ks0 + 2u;
    tf_round(x0, x1, 13); tf_round(x0, x1, 15); tf_round(x0, x1, 26); tf_round(x0, x1, 6);
    x0 += ks0; x1 += ks1 + 3u;
    tf_round(x0, x1, 17); tf_round(x0, x1, 29); tf_round(x0, x1, 16); tf_round(x0, x1, 24);
    x0 += ks1; x1 += ks2 + 4u;
    tf_round(x0, x1, 13); tf_round(x0, x1, 15); tf_round(x0, x1, 26); tf_round(x0, x1, 6);
    x0 += ks2; x1 += ks0 + 5u;
    return make_uint2(x0, x1);
}

// ---------------------------------------------------------------------------
// Kernel: zero routing counters
// ---------------------------------------------------------------------------
__global__ void zero_counts_kernel() {
    if (threadIdx.x < N_EXPERTS) d_counts[threadIdx.x] = 0;
}

// ---------------------------------------------------------------------------
// Kernel: policy head + Gumbel top-2 routing.  One block per token.
// ---------------------------------------------------------------------------
__global__ __launch_bounds__(256)
void routing_kernel(const float* __restrict__ x,
                    const float* __restrict__ pw1, const float* __restrict__ pb1,
                    const float* __restrict__ pg1, const float* __restrict__ pbb1,
                    const float* __restrict__ pw2, const float* __restrict__ pb2) {
    __shared__ float xs[D_MODEL];
    __shared__ float red[256];
    __shared__ float gbuf[D_HALF];
    __shared__ float scores[N_EXPERTS];

    int token = blockIdx.x;
    int t = threadIdx.x;

    for (int i = t; i < D_MODEL; i += 256) xs[i] = x[(size_t)token * D_MODEL + i];
    __syncthreads();

    float acc = pb1[t];
    #pragma unroll 4
    for (int k = 0; k < D_MODEL; k++)
        acc = fmaf(xs[k], pw1[k * D_HALF + t], acc);

    float mean = reduce256(acc, red) * (1.0f / D_HALF);
    float d = acc - mean;
    float var = reduce256(d * d, red) * (1.0f / D_HALF);
    float hn = d * rsqrtf(var + 1e-5f) * pg1[t] + pbb1[t];
    gbuf[t] = gelu_f(hn);
    __syncthreads();

    if (t < N_EXPERTS) {
        float lg = pb2[t];
        #pragma unroll 4
        for (int j = 0; j < D_HALF; j++)
            lg = fmaf(gbuf[j], pw2[j * N_EXPERTS + t], lg);

        // partitionable threefry: counter (0, i), bits = out0 ^ out1
        uint32_t idx = (uint32_t)(token * N_EXPERTS + t);
        uint2 r = threefry2x32(0u, 42u, 0u, idx);
        uint32_t bits = r.x ^ r.y;
        float u = __uint_as_float((bits >> 9) | 0x3f800000u) - 1.0f;
        float gn = -logf(-logf(u + 1e-10f) + 1e-10f);
        scores[t] = lg + gn;
    }
    __syncthreads();

    if (t == 0) {
        int e1 = 0; float v1 = scores[0];
        #pragma unroll
        for (int e = 1; e < N_EXPERTS; e++)
            if (scores[e] > v1) { v1 = scores[e]; e1 = e; }
        int e2 = -1; float v2 = -1e30f;
        #pragma unroll
        for (int e = 0; e < N_EXPERTS; e++) {
            if (e == e1) continue;
            if (scores[e] > v2) { v2 = scores[e]; e2 = e; }
        }
        int p = atomicAdd(&d_counts[e1], 1);
        d_tlist[e1 * CAP + p] = token;
        p = atomicAdd(&d_counts[e2], 1);
        d_tlist[e2 * CAP + p] = token;
    }
}

// ---------------------------------------------------------------------------
// Kernel: gather selected token rows
// ---------------------------------------------------------------------------
__global__ void gather_kernel(const float* __restrict__ x) {
    int m = blockIdx.x, e = blockIdx.y;
    if (m >= d_counts[e]) return;
    int token = d_tlist[e * CAP + m];
    const float4* src = (const float4*)(x + (size_t)token * D_MODEL);
    float4* dst = (float4*)(d_Xg + ((size_t)e * CAP + m) * D_MODEL);
    dst[threadIdx.x] = src[threadIdx.x];
}

// ---------------------------------------------------------------------------
// tf32 tensor-core GEMM, cp.async 2-stage ping-pong, 2 CTAs/SM:
//   C[e] = act(A[e] @ B[e] + bias[e]),  A: [M_e,K] rm,  B: [K,N] rm.
// Tile 128x128x32; 8 warps as 4(m) x 2(n); warp tile 32x64 = 2x8 m16n8k8.
// grid (N/128, CAP/128, N_EXPERTS), 256 threads, dyn smem = GEMM_SMEM.
// ---------------------------------------------------------------------------
template<int ACT>
__global__ __launch_bounds__(256, 2)
void gemm_mma(const float* __restrict__ Aall, long strideA,
              const float* __restrict__ Ball, long strideB,
              const float* __restrict__ biasAll, long strideBias,
              float* __restrict__ Call, long strideC,
              int N, int K) {
    extern __shared__ uint32_t sm[];

    int e = blockIdx.z;
    int M = d_counts[e];
    int m0 = blockIdx.y * 128;
    if (m0 >= M) return;
    int n0 = blockIdx.x * 128;

    const float* A    = Aall   + (long)e * strideA;
    const float* B    = Ball   + (long)e * strideB;
    const float* bias = biasAll + (long)e * strideBias;
    float* C          = Call   + (long)e * strideC;

    int tid  = threadIdx.x;
    int wid  = tid >> 5;
    int lane = tid & 31;
    int wm = wid >> 1;            // 0..3  (m)
    int wn = wid & 1;             // 0..1  (n)
    int gid = lane >> 2;          // 0..7
    int tig = lane & 3;           // 0..3

    float acc[2][8][4];
    #pragma unroll
    for (int i = 0; i < 2; i++)
        #pragma unroll
        for (int j = 0; j < 8; j++)
            #pragma unroll
            for (int c = 0; c < 4; c++) acc[i][j][c] = 0.0f;

    const int NC = K >> 5;

    auto load_tile = [&](int chunk) {
        uint32_t* As = sm + (chunk & 1) * STAGE_WORDS;
        uint32_t* Bs = As + A_WORDS;
        int k0 = chunk << 5;
        #pragma unroll
        for (int i = 0; i < 4; i++) {
            int idx = i * 256 + tid;
            int r = idx >> 3, c4 = (idx & 7) << 2;
            int rr = m0 + r;
            int sz = (rr < M) ? 16 : 0;
            int rc = (rr < M) ? rr : 0;
            cp16(smem_u32(&As[r * AS_STRIDE + c4]),
                 &A[(long)rc * K + k0 + c4], sz);
        }
        #pragma unroll
        for (int i = 0; i < 4; i++) {
            int idx = i * 256 + tid;
            int r = idx >> 5, c4 = (idx & 31) << 2;
            cp16f(smem_u32(&Bs[r * BS_STRIDE + c4]),
                  &B[(long)(k0 + r) * N + n0 + c4]);
        }
        cp_commit();
    };

    load_tile(0);

    for (int chunk = 0; chunk < NC; chunk++) {
        // prefetch next chunk into the other buffer (safe: the trailing
        // __syncthreads of the previous iteration guarantees all warps are
        // done reading it)
        if (chunk + 1 < NC) { load_tile(chunk + 1); cp_wait<1>(); }
        else                { cp_wait<0>(); }
        __syncthreads();

        uint32_t* As = sm + (chunk & 1) * STAGE_WORDS;
        uint32_t* Bs = As + A_WORDS;

        #pragma unroll
        for (int ks = 0; ks < 4; ks++) {
            int kk = ks * 8;
            uint32_t a[2][4];
            #pragma unroll
            for (int mt = 0; mt < 2; mt++) {
                int row = wm * 32 + mt * 16 + gid;
                const uint32_t* ap = &As[row * AS_STRIDE + kk + tig];
                a[mt][0] = ap[0];
                a[mt][1] = ap[8 * AS_STRIDE];
                a[mt][2] = ap[4];
                a[mt][3] = ap[8 * AS_STRIDE + 4];
            }
            #pragma unroll
            for (int nt = 0; nt < 8; nt++) {
                int col = wn * 64 + nt * 8 + gid;
                uint32_t b[2];
                b[0] = Bs[(kk + tig) * BS_STRIDE + col];
                b[1] = Bs[(kk + tig + 4) * BS_STRIDE + col];
                mma_tf32_16n8k8(acc[0][nt], a[0], b);
                mma_tf32_16n8k8(acc[1][nt], a[1], b);
            }
        }
        __syncthreads();   // all warps done with this buffer before next load
    }

    // epilogue: bias + act, float2 stores
    #pragma unroll
    for (int mt = 0; mt < 2; mt++) {
        #pragma unroll
        for (int nt = 0; nt < 8; nt++) {
            int col = n0 + wn * 64 + nt * 8 + 2 * tig;
            float b0 = bias[col], b1 = bias[col + 1];
            int r0 = m0 + wm * 32 + mt * 16 + gid;
            int r1 = r0 + 8;
            if (r0 < M) {
                float v0 = acc[mt][nt][0] + b0;
                float v1 = acc[mt][nt][1] + b1;
                if (ACT == 1) { v0 = gelu_f(v0); v1 = gelu_f(v1); }
                *(float2*)&C[(long)r0 * N + col] = make_float2(v0, v1);
            }
            if (r1 < M) {
                float v0 = acc[mt][nt][2] + b0;
                float v1 = acc[mt][nt][3] + b1;
                if (ACT == 1) { v0 = gelu_f(v0); v1 = gelu_f(v1); }
                *(float2*)&C[(long)r1 * N + col] = make_float2(v0, v1);
            }
        }
    }
}

// ---------------------------------------------------------------------------
// Kernel: per-row LN of h2, sigmoid gate from h, residual update.
// ---------------------------------------------------------------------------
__global__ __launch_bounds__(256)
void lngate_kernel(const float* __restrict__ ng, const float* __restrict__ nb,
                   const float* __restrict__ gwv) {
    __shared__ float red[256];
    int m = blockIdx.x, e = blockIdx.y;
    if (m >= d_counts[e]) return;
    int t = threadIdx.x;

    float* h = d_H + ((size_t)e * CAP + m) * D_FF;
    const float* h2 = d_H2 + ((size_t)e * CAP + m) * D_FF;
    const float* ng_e = ng + (size_t)e * (N_LAYERS * D_FF);
    const float* nb_e = nb + (size_t)e * (N_LAYERS * D_FF);
    const float* gw_e = gwv + (size_t)e * (N_LAYERS * D_FF);

    float hv[4], h2v[4];
    float s = 0.f, sq = 0.f, dot = 0.f;
    #pragma unroll
    for (int c = 0; c < 4; c++) {
        int i = t + c * 256;
        hv[c] = h[i];
        h2v[c] = h2[i];
        s += h2v[c];
        dot = fmaf(hv[c], gw_e[i], dot);
    }
    float mean = reduce256(s, red) * (1.0f / D_FF);
    #pragma unroll
    for (int c = 0; c < 4; c++) { float d = h2v[c] - mean; sq += d * d; }
    float var = reduce256(sq, red) * (1.0f / D_FF);
    float dtot = reduce256(dot, red);
    float gate = 1.0f / (1.0f + expf(-dtot));
    float rstd = rsqrtf(var + 1e-5f);

    #pragma unroll
    for (int c = 0; c < 4; c++) {
        int i = t + c * 256;
        float hn = (h2v[c] - mean) * rstd * ng_e[i] + nb_e[i];
        h[i] = hv[c] + gate * hn;
    }
}

// ---------------------------------------------------------------------------
// Kernel: final residual LN + scatter-add into output.
// ---------------------------------------------------------------------------
__global__ __launch_bounds__(256)
void final_kernel(const float* __restrict__ x,
                  const float* __restrict__ fng, const float* __restrict__ fnb,
                  float* __restrict__ out) {
    __shared__ float red[256];
    int m = blockIdx.x, e = blockIdx.y;
    if (m >= d_counts[e]) return;
    int t = threadIdx.x;
    int token = d_tlist[e * CAP + m];

    const float* orow = d_Ob + ((size_t)e * CAP + m) * D_MODEL;
    const float* xrow = x + (size_t)token * D_MODEL;
    const float* g = fng + (size_t)e * D_MODEL;
    const float* b = fnb + (size_t)e * D_MODEL;

    float v[2];
    float s = 0.f, sq = 0.f;
    #pragma unroll
    for (int c = 0; c < 2; c++) {
        int i = t + c * 256;
        v[c] = xrow[i] + orow[i];
        s += v[c];
    }
    float mean = reduce256(s, red) * (1.0f / D_MODEL);
    #pragma unroll
    for (int c = 0; c < 2; c++) { float d = v[c] - mean; sq += d * d; }
    float var = reduce256(sq, red) * (1.0f / D_MODEL);
    float rstd = rsqrtf(var + 1e-5f);

    #pragma unroll
    for (int c = 0; c < 2; c++) {
        int i = t + c * 256;
        float y = (v[c] - mean) * rstd * g[i] + b[i];
        atomicAdd(&out[(size_t)token * D_MODEL + i], y);
    }
}

// ---------------------------------------------------------------------------
// Launch
// ---------------------------------------------------------------------------
extern "C" void kernel_launch(void* const* d_in, const int* in_sizes, int n_in,
                              void* d_out, int out_size) {
    const float* x    = (const float*)d_in[0];
    const float* pw1  = (const float*)d_in[1];
    const float* pb1  = (const float*)d_in[2];
    const float* pg1  = (const float*)d_in[3];
    const float* pbb1 = (const float*)d_in[4];
    const float* pw2  = (const float*)d_in[5];
    const float* pb2  = (const float*)d_in[6];
    const float* Win  = (const float*)d_in[7];
    const float* b_in = (const float*)d_in[8];
    const float* W1   = (const float*)d_in[9];
    const float* b1   = (const float*)d_in[10];
    const float* W2   = (const float*)d_in[11];
    const float* b2   = (const float*)d_in[12];
    const float* ng   = (const float*)d_in[13];
    const float* nb   = (const float*)d_in[14];
    const float* gw   = (const float*)d_in[15];
    const float* Wout = (const float*)d_in[16];
    const float* bout = (const float*)d_in[17];
    const float* fng  = (const float*)d_in[18];
    const float* fnb  = (const float*)d_in[19];
    float* out = (float*)d_out;

    float *Xg, *H, *A2, *H2, *Ob;
    cudaGetSymbolAddress((void**)&Xg, d_Xg);
    cudaGetSymbolAddress((void**)&H,  d_H);
    cudaGetSymbolAddress((void**)&A2, d_A2);
    cudaGetSymbolAddress((void**)&H2, d_H2);
    cudaGetSymbolAddress((void**)&Ob, d_Ob);

    cudaFuncSetAttribute(gemm_mma<0>, cudaFuncAttributeMaxDynamicSharedMemorySize, GEMM_SMEM);
    cudaFuncSetAttribute(gemm_mma<1>, cudaFuncAttributeMaxDynamicSharedMemorySize, GEMM_SMEM);

    cudaMemsetAsync(out, 0, (size_t)out_size * sizeof(float), 0);
    zero_counts_kernel<<<1, 32>>>();
    routing_kernel<<<N_TOKENS, 256>>>(x, pw1, pb1, pg1, pbb1, pw2, pb2);
    gather_kernel<<<dim3(CAP, N_EXPERTS), 128>>>(x);

    // H = Xg @ Win + b_in                  [M,512] x [512,1024]
    gemm_mma<0><<<dim3(D_FF / 128, CAP / 128, N_EXPERTS), 256, GEMM_SMEM>>>(
        Xg, (long)CAP * D_MODEL,
        Win, (long)D_MODEL * D_FF,
        b_in, (long)D_FF,
        H, (long)CAP * D_FF,
        D_FF, D_MODEL);

    for (int l = 0; l < N_LAYERS; l++) {
        // A2 = gelu(H @ W1[l] + b1[l])     [M,1024] x [1024,2048]
        gemm_mma<1><<<dim3(D_FF2 / 128, CAP / 128, N_EXPERTS), 256, GEMM_SMEM>>>(
            H, (long)CAP * D_FF,
            W1 + (long)l * D_FF * D_FF2, (long)N_LAYERS * D_FF * D_FF2,
            b1 + (long)l * D_FF2, (long)N_LAYERS * D_FF2,
            A2, (long)CAP * D_FF2,
            D_FF2, D_FF);
        // H2 = A2 @ W2[l] + b2[l]          [M,2048] x [2048,1024]
        gemm_mma<0><<<dim3(D_FF / 128, CAP / 128, N_EXPERTS), 256, GEMM_SMEM>>>(
            A2, (long)CAP * D_FF2,
            W2 + (long)l * D_FF2 * D_FF, (long)N_LAYERS * D_FF2 * D_FF,
            b2 + (long)l * D_FF, (long)N_LAYERS * D_FF,
            H2, (long)CAP * D_FF,
            D_FF, D_FF2);
        lngate_kernel<<<dim3(CAP, N_EXPERTS), 256>>>(
            ng + (long)l * D_FF, nb + (long)l * D_FF, gw + (long)l * D_FF);
    }

    // Ob = H @ Wout + bout                 [M,1024] x [1024,512]
    gemm_mma<0><<<dim3(D_MODEL / 128, CAP / 128, N_EXPERTS), 256, GEMM_SMEM>>>(
        H, (long)CAP * D_FF,
        Wout, (long)D_FF * D_MODEL,
        bout, (long)D_MODEL,
        Ob, (long)CAP * D_MODEL,
        D_MODEL, D_FF);

    final_kernel<<<dim3(CAP, N_EXPERTS), 256>>>(x, fng, fnb, out);
}